// round 2
// baseline (speedup 1.0000x reference)
#include <cuda_runtime.h>

// Problem constants
#define Bn   2
#define Sn   2048
#define Dm   1024
#define Hn   16
#define DKc  64
#define Mrows 4096          // B*S
#define TC   3072           // 3*Dm

// Scratch (allocation-free: __device__ globals)
__device__ float g_qkv[(size_t)Mrows * TC];    // 50.3 MB
__device__ float g_attn[(size_t)Mrows * Dm];   // 16.8 MB

// ---------------------------------------------------------------------------
// SGEMM with bias: C[M,N] = A[M,K] @ B[K,N] + bias[N]
// 128x128x16 tiles, 256 threads, 8x8 micro-tile split as (4 + 4 offset 64)
// ---------------------------------------------------------------------------
__global__ __launch_bounds__(256, 2)
void sgemm_bias_kernel(const float* __restrict__ A, const float* __restrict__ B,
                       const float* __restrict__ bias, float* __restrict__ C,
                       int M, int N, int K)
{
    __shared__ float As[16][128];   // As[k][m] (transposed A tile)
    __shared__ float Bs[16][128];   // Bs[k][n]

    const int t  = threadIdx.x;
    const int tx = t & 15;
    const int ty = t >> 4;
    const int brow = blockIdx.y << 7;
    const int bcol = blockIdx.x << 7;

    // load mapping
    const int la_r = t >> 2;          // 0..63
    const int la_k = (t & 3) << 2;    // 0,4,8,12
    const int lb_k = t >> 5;          // 0..7
    const int lb_c = (t & 31) << 2;   // 0..124

    float acc[8][8];
#pragma unroll
    for (int i = 0; i < 8; i++)
#pragma unroll
        for (int j = 0; j < 8; j++) acc[i][j] = 0.f;

    for (int k0 = 0; k0 < K; k0 += 16) {
        float4 a0 = *(const float4*)(A + (size_t)(brow + la_r) * K + k0 + la_k);
        float4 a1 = *(const float4*)(A + (size_t)(brow + la_r + 64) * K + k0 + la_k);
        float4 b0 = *(const float4*)(B + (size_t)(k0 + lb_k) * N + bcol + lb_c);
        float4 b1 = *(const float4*)(B + (size_t)(k0 + lb_k + 8) * N + bcol + lb_c);

        __syncthreads();   // previous iteration's compute must finish
        As[la_k + 0][la_r]      = a0.x;
        As[la_k + 1][la_r]      = a0.y;
        As[la_k + 2][la_r]      = a0.z;
        As[la_k + 3][la_r]      = a0.w;
        As[la_k + 0][la_r + 64] = a1.x;
        As[la_k + 1][la_r + 64] = a1.y;
        As[la_k + 2][la_r + 64] = a1.z;
        As[la_k + 3][la_r + 64] = a1.w;
        *(float4*)&Bs[lb_k][lb_c]     = b0;
        *(float4*)&Bs[lb_k + 8][lb_c] = b1;
        __syncthreads();

#pragma unroll
        for (int k = 0; k < 16; k++) {
            float4 ra0 = *(float4*)&As[k][(ty << 2)];
            float4 ra1 = *(float4*)&As[k][64 + (ty << 2)];
            float4 rb0 = *(float4*)&Bs[k][(tx << 2)];
            float4 rb1 = *(float4*)&Bs[k][64 + (tx << 2)];
            float ra[8] = {ra0.x, ra0.y, ra0.z, ra0.w, ra1.x, ra1.y, ra1.z, ra1.w};
            float rb[8] = {rb0.x, rb0.y, rb0.z, rb0.w, rb1.x, rb1.y, rb1.z, rb1.w};
#pragma unroll
            for (int i = 0; i < 8; i++)
#pragma unroll
                for (int j = 0; j < 8; j++)
                    acc[i][j] = fmaf(ra[i], rb[j], acc[i][j]);
        }
    }

    float4 bv0 = *(const float4*)(bias + bcol + (tx << 2));
    float4 bv1 = *(const float4*)(bias + bcol + 64 + (tx << 2));
    float bb[8] = {bv0.x, bv0.y, bv0.z, bv0.w, bv1.x, bv1.y, bv1.z, bv1.w};

#pragma unroll
    for (int i = 0; i < 8; i++) {
        int r = brow + ((i < 4) ? ((ty << 2) + i) : (64 + (ty << 2) + i - 4));
        float4 o0 = make_float4(acc[i][0] + bb[0], acc[i][1] + bb[1],
                                acc[i][2] + bb[2], acc[i][3] + bb[3]);
        float4 o1 = make_float4(acc[i][4] + bb[4], acc[i][5] + bb[5],
                                acc[i][6] + bb[6], acc[i][7] + bb[7]);
        *(float4*)(C + (size_t)r * N + bcol + (tx << 2))      = o0;
        *(float4*)(C + (size_t)r * N + bcol + 64 + (tx << 2)) = o1;
    }
}

// ---------------------------------------------------------------------------
// Flash-style causal attention, fp32.
// One block per (b, h, 64-row q tile). 256 threads; each owns 4 rows x 4 cols
// (rows = ty*4+i, cols = tx + 16*m). 64x64 tiles in smem, XOR-swizzled at
// float4 granularity: slot(row, c4) = c4 ^ (row & 15).
// ---------------------------------------------------------------------------
__global__ __launch_bounds__(256, 2)
void attn_kernel(const float* __restrict__ qkv, float* __restrict__ outp)
{
    __shared__ float4 Qs[64][16];
    __shared__ float4 KPs[64][16];   // K tile, later aliased by P
    __shared__ float4 Vs[64][16];

    const int t  = threadIdx.x;
    const int tx = t & 15;
    const int ty = t >> 4;
    const int qt = (int)(gridDim.x - 1u - blockIdx.x);  // heavy tiles first
    const int h  = blockIdx.y;
    const int b  = blockIdx.z;
    const int qrow0 = b * Sn + qt * 64;

    const int lr = t >> 4;    // row per load pass
    const int lk = t & 15;    // float4 column

    // load Q tile once (swizzled)
#pragma unroll
    for (int p = 0; p < 4; p++) {
        int j = lr + (p << 4);
        Qs[j][lk ^ (j & 15)] =
            *(const float4*)(qkv + (size_t)(qrow0 + j) * TC + h * DKc + (lk << 2));
    }

    float o[4][4];
    float mprev[4], l[4];
#pragma unroll
    for (int i = 0; i < 4; i++) {
        mprev[i] = -1e30f;
        l[i] = 0.f;
#pragma unroll
        for (int m = 0; m < 4; m++) o[i][m] = 0.f;
    }

    for (int jt = 0; jt <= qt; jt++) {
        const int krow0 = b * Sn + jt * 64;
        __syncthreads();   // previous AV must be done with KPs/Vs
#pragma unroll
        for (int p = 0; p < 4; p++) {
            int j = lr + (p << 4);
            size_t base = (size_t)(krow0 + j) * TC + h * DKc + (lk << 2);
            KPs[j][lk ^ (j & 15)] = *(const float4*)(qkv + base + Dm);      // K
            Vs[j][lk ^ (j & 15)]  = *(const float4*)(qkv + base + 2 * Dm);  // V
        }
        __syncthreads();

        // ---- S = Q K^T ----
        float s[4][4];
#pragma unroll
        for (int i = 0; i < 4; i++)
#pragma unroll
            for (int m = 0; m < 4; m++) s[i][m] = 0.f;

#pragma unroll
        for (int k4 = 0; k4 < 16; k4++) {
            float4 q[4], kk[4];
#pragma unroll
            for (int i = 0; i < 4; i++) {
                int r = (ty << 2) + i;
                q[i] = Qs[r][k4 ^ (r & 15)];
            }
#pragma unroll
            for (int m = 0; m < 4; m++)
                kk[m] = KPs[tx + (m << 4)][k4 ^ tx];
#pragma unroll
            for (int i = 0; i < 4; i++)
#pragma unroll
                for (int m = 0; m < 4; m++) {
                    s[i][m] = fmaf(q[i].x, kk[m].x, s[i][m]);
                    s[i][m] = fmaf(q[i].y, kk[m].y, s[i][m]);
                    s[i][m] = fmaf(q[i].z, kk[m].z, s[i][m]);
                    s[i][m] = fmaf(q[i].w, kk[m].w, s[i][m]);
                }
        }

        // ---- scale + causal mask + online softmax ----
        const bool diag = (jt == qt);
#pragma unroll
        for (int i = 0; i < 4; i++) {
            int r = (ty << 2) + i;
#pragma unroll
            for (int m = 0; m < 4; m++) {
                float v = s[i][m] * 0.125f;          // 1/sqrt(64)
                if (diag && (tx + (m << 4)) > r) v = -1e30f;
                s[i][m] = v;
            }
            float tmax = fmaxf(fmaxf(s[i][0], s[i][1]), fmaxf(s[i][2], s[i][3]));
#pragma unroll
            for (int off = 1; off < 16; off <<= 1)
                tmax = fmaxf(tmax, __shfl_xor_sync(0xffffffffu, tmax, off));
            float mnew = fmaxf(mprev[i], tmax);
            float corr = __expf(mprev[i] - mnew);
            float ts = 0.f;
#pragma unroll
            for (int m = 0; m < 4; m++) {
                s[i][m] = __expf(s[i][m] - mnew);
                ts += s[i][m];
            }
#pragma unroll
            for (int off = 1; off < 16; off <<= 1)
                ts += __shfl_xor_sync(0xffffffffu, ts, off);
            l[i] = l[i] * corr + ts;
            mprev[i] = mnew;
#pragma unroll
            for (int m = 0; m < 4; m++) o[i][m] *= corr;
        }

        __syncthreads();   // all threads done reading KPs (K)
        // ---- write P into KPs (aliased) ----
#pragma unroll
        for (int i = 0; i < 4; i++) {
            int r = (ty << 2) + i;
#pragma unroll
            for (int m = 0; m < 4; m++) {
                int c = tx + (m << 4);
                ((float*)&KPs[r][(c >> 2) ^ (r & 15)])[c & 3] = s[i][m];
            }
        }
        __syncthreads();

        // ---- O += P V ----
#pragma unroll
        for (int j4 = 0; j4 < 16; j4++) {
            float4 pp[4];
#pragma unroll
            for (int i = 0; i < 4; i++) {
                int r = (ty << 2) + i;
                pp[i] = KPs[r][j4 ^ (r & 15)];
            }
#pragma unroll
            for (int jj = 0; jj < 4; jj++) {
                int j = (j4 << 2) + jj;
                float pv[4] = { ((float*)&pp[0])[jj], ((float*)&pp[1])[jj],
                                ((float*)&pp[2])[jj], ((float*)&pp[3])[jj] };
                float vv[4];
#pragma unroll
                for (int m = 0; m < 4; m++) {
                    int c = tx + (m << 4);
                    vv[m] = ((const float*)&Vs[j][(c >> 2) ^ (j & 15)])[c & 3];
                }
#pragma unroll
                for (int i = 0; i < 4; i++)
#pragma unroll
                    for (int m = 0; m < 4; m++)
                        o[i][m] = fmaf(pv[i], vv[m], o[i][m]);
            }
        }
    }

    // ---- normalize and write (head-merged layout [B*S, Dm]) ----
#pragma unroll
    for (int i = 0; i < 4; i++) {
        int r = (ty << 2) + i;
        float inv = 1.f / l[i];
#pragma unroll
        for (int m = 0; m < 4; m++) {
            int c = tx + (m << 4);
            outp[(size_t)(qrow0 + r) * Dm + h * DKc + c] = o[i][m] * inv;
        }
    }
}

// ---------------------------------------------------------------------------
extern "C" void kernel_launch(void* const* d_in, const int* in_sizes, int n_in,
                              void* d_out, int out_size)
{
    const float* x     = (const float*)d_in[0];
    // d_in[1] = causal mask (int32) — causality hardcoded, unused
    const float* w_qkv = (const float*)d_in[2];
    const float* b_qkv = (const float*)d_in[3];
    const float* w_out = (const float*)d_in[4];
    const float* b_out = (const float*)d_in[5];
    float* out = (float*)d_out;

    float *qkv = nullptr, *attn = nullptr;
    cudaGetSymbolAddress((void**)&qkv, g_qkv);
    cudaGetSymbolAddress((void**)&attn, g_attn);

    dim3 thr(256);
    // 1) QKV projection: [4096,1024] @ [1024,3072] + b
    sgemm_bias_kernel<<<dim3(TC / 128, Mrows / 128), thr>>>(
        x, w_qkv, b_qkv, qkv, Mrows, TC, Dm);
    // 2) causal flash attention per (qtile, head, batch)
    attn_kernel<<<dim3(Sn / 64, Hn, Bn), thr>>>(qkv, attn);
    // 3) output projection: [4096,1024] @ [1024,1024] + b
    sgemm_bias_kernel<<<dim3(Dm / 128, Mrows / 128), thr>>>(
        attn, w_out, b_out, out, Mrows, Dm, Dm);
}

// round 5
// speedup vs baseline: 1.4098x; 1.4098x over previous
#include <cuda_runtime.h>
#include <cuda_bf16.h>
#include <cstdint>

// Problem constants
#define Bn   2
#define Sn   2048
#define Dm   1024
#define Hn   16
#define DKc  64
#define Mrows 4096          // B*S
#define TC   3072           // 3*Dm

// Scratch (allocation-free: __device__ globals)
__device__ float g_qkv[(size_t)Mrows * TC];    // 50.3 MB
__device__ float g_attn[(size_t)Mrows * Dm];   // 16.8 MB
__device__ __nv_bfloat16 g_ah[(size_t)Mrows * Dm];  // A hi
__device__ __nv_bfloat16 g_al[(size_t)Mrows * Dm];  // A lo
__device__ __nv_bfloat16 g_bh[(size_t)TC * Dm];     // B^T hi
__device__ __nv_bfloat16 g_bl[(size_t)TC * Dm];     // B^T lo

// ---------------------------------------------------------------------------
// PTX helpers (baseline-PTX only: cp.async, ldmatrix, mma.sync — no 'a' feats)
// ---------------------------------------------------------------------------
__device__ __forceinline__ uint32_t smem_u32(const void* p) {
    return (uint32_t)__cvta_generic_to_shared(p);
}
#define CP_ASYNC16(dst, src) \
    asm volatile("cp.async.cg.shared.global [%0], [%1], 16;" :: "r"(dst), "l"(src))
#define CP_COMMIT() asm volatile("cp.async.commit_group;" ::: "memory")
#define CP_WAIT2()  asm volatile("cp.async.wait_group 2;" ::: "memory")

__device__ __forceinline__ void ldsm4(uint32_t* r, uint32_t addr) {
    asm volatile("ldmatrix.sync.aligned.m8n8.x4.shared.b16 {%0,%1,%2,%3}, [%4];"
        : "=r"(r[0]), "=r"(r[1]), "=r"(r[2]), "=r"(r[3]) : "r"(addr));
}
__device__ __forceinline__ void mma16816(float* d, const uint32_t* a, const uint32_t* b) {
    asm volatile(
        "mma.sync.aligned.m16n8k16.row.col.f32.bf16.bf16.f32 "
        "{%0,%1,%2,%3}, {%4,%5,%6,%7}, {%8,%9}, {%0,%1,%2,%3};"
        : "+f"(d[0]), "+f"(d[1]), "+f"(d[2]), "+f"(d[3])
        : "r"(a[0]), "r"(a[1]), "r"(a[2]), "r"(a[3]), "r"(b[0]), "r"(b[1]));
}

// ---------------------------------------------------------------------------
// fp32 -> bf16 hi/lo split (straight copy)
// ---------------------------------------------------------------------------
__global__ void split_kernel(const float* __restrict__ in,
                             __nv_bfloat16* __restrict__ hi,
                             __nv_bfloat16* __restrict__ lo, int n4)
{
    int i = blockIdx.x * blockDim.x + threadIdx.x;
    if (i >= n4) return;
    float4 v = ((const float4*)in)[i];
    float vv[4] = {v.x, v.y, v.z, v.w};
    __nv_bfloat162 h2[2], l2[2];
#pragma unroll
    for (int p = 0; p < 2; p++) {
        __nv_bfloat16 h0 = __float2bfloat16(vv[2*p]);
        __nv_bfloat16 h1 = __float2bfloat16(vv[2*p+1]);
        __nv_bfloat16 l0 = __float2bfloat16(vv[2*p]   - __bfloat162float(h0));
        __nv_bfloat16 l1 = __float2bfloat16(vv[2*p+1] - __bfloat162float(h1));
        h2[p] = __nv_bfloat162(h0, h1);
        l2[p] = __nv_bfloat162(l0, l1);
    }
    ((__nv_bfloat162*)hi)[2*i]   = h2[0];
    ((__nv_bfloat162*)hi)[2*i+1] = h2[1];
    ((__nv_bfloat162*)lo)[2*i]   = l2[0];
    ((__nv_bfloat162*)lo)[2*i+1] = l2[1];
}

// ---------------------------------------------------------------------------
// fp32 [K][N] -> bf16 hi/lo [N][K] (transpose + split), 32x32 tiles
// ---------------------------------------------------------------------------
__global__ void transpose_split_kernel(const float* __restrict__ in,
                                       __nv_bfloat16* __restrict__ hi,
                                       __nv_bfloat16* __restrict__ lo,
                                       int K, int N)
{
    __shared__ float t[32][33];
    int bx = blockIdx.x << 5;   // N offset
    int by = blockIdx.y << 5;   // K offset
    int x = threadIdx.x;
    int y = threadIdx.y;
#pragma unroll
    for (int i = 0; i < 32; i += 8)
        t[y + i][x] = in[(size_t)(by + y + i) * N + bx + x];
    __syncthreads();
#pragma unroll
    for (int i = 0; i < 32; i += 8) {
        float v = t[x][y + i];
        __nv_bfloat16 h = __float2bfloat16(v);
        __nv_bfloat16 l = __float2bfloat16(v - __bfloat162float(h));
        size_t o = (size_t)(bx + y + i) * K + by + x;
        hi[o] = h;
        lo[o] = l;
    }
}

// ---------------------------------------------------------------------------
// HMMA bf16-split GEMM: C[M,N] = A[M,K] @ BT[N,K]^T + bias
// 128x128x32 CTA tile, 8 warps of 64x32, 4-stage cp.async pipeline.
// 3 term-pairs per chunk: AhBh, AhBl, AlBh (fp32-equivalent precision).
// Tile smem layout: [128 rows][32 cols bf16] = 64B rows;
// swizzle: 16B-granule column c16 ^= (row>>1)&3  (ldmatrix conflict-free).
// ---------------------------------------------------------------------------
#define SUB_BYTES  8192                    // one 128x32 bf16 tile
#define STAGE_BYTES (4 * SUB_BYTES)        // Ah | Al | Bh | Bl
#define NSTAGE 4
#define GEMM_DSMEM (NSTAGE * STAGE_BYTES)  // 128 KB

__device__ __forceinline__ void load_chunk(
    uint32_t so, int tid, int chunk,
    const __nv_bfloat16* __restrict__ Ah, const __nv_bfloat16* __restrict__ Al,
    const __nv_bfloat16* __restrict__ Bh, const __nv_bfloat16* __restrict__ Bl,
    int brow, int bcol, int K)
{
    const int k0 = chunk << 5;           // 32 per chunk
#pragma unroll
    for (int p = 0; p < 2; p++) {
        int r   = (tid >> 2) + (p << 6); // 0..127
        int c16 = tid & 3;               // 16B granule (8 bf16)
        uint32_t dst = so + r * 64 + ((c16 ^ ((r >> 1) & 3)) << 4);
        size_t ga = (size_t)(brow + r) * K + k0 + (c16 << 3);
        size_t gb = (size_t)(bcol + r) * K + k0 + (c16 << 3);
        CP_ASYNC16(dst,                 Ah + ga);
        CP_ASYNC16(dst + SUB_BYTES,     Al + ga);
        CP_ASYNC16(dst + 2 * SUB_BYTES, Bh + gb);
        CP_ASYNC16(dst + 3 * SUB_BYTES, Bl + gb);
    }
}

__global__ __launch_bounds__(256, 1)
void gemm_bf16x3(const __nv_bfloat16* __restrict__ Ah, const __nv_bfloat16* __restrict__ Al,
                 const __nv_bfloat16* __restrict__ Bh, const __nv_bfloat16* __restrict__ Bl,
                 const float* __restrict__ bias, float* __restrict__ C,
                 int N, int K)
{
    extern __shared__ char dsmem_raw[];
    const uint32_t sb = smem_u32(dsmem_raw);

    const int tid  = threadIdx.x;
    const int wid  = tid >> 5;
    const int lane = tid & 31;
    const int brow = blockIdx.y << 7;
    const int bcol = blockIdx.x << 7;
    const int NCHUNK = K >> 5;

    const int m0 = (wid & 1) << 6;   // 0 or 64
    const int n0 = (wid >> 1) << 5;  // 0,32,64,96

    float acc[4][4][4];
#pragma unroll
    for (int mt = 0; mt < 4; mt++)
#pragma unroll
        for (int nt = 0; nt < 4; nt++)
#pragma unroll
            for (int e = 0; e < 4; e++) acc[mt][nt][e] = 0.f;

    // ldmatrix per-thread row/swizzle precompute
    // A (x4): row = m0 + mt*16 + (lane&15), c16half = lane>>4
    int arow[4], asel[4];
#pragma unroll
    for (int mt = 0; mt < 4; mt++) {
        arow[mt] = m0 + mt * 16 + (lane & 15);
        asel[mt] = (arow[mt] >> 1) & 3;
    }
    // B (x4, 2 n8-tiles per load): g = lane>>3; nt = g>>1; khalf = g&1
    int brow_f[2], bsel[2], bkh = (lane >> 3) & 1;
#pragma unroll
    for (int np = 0; np < 2; np++) {
        brow_f[np] = n0 + np * 16 + ((lane >> 4) << 3) + (lane & 7);
        bsel[np] = (brow_f[np] >> 1) & 3;
    }

    // prologue: stages 0..2
#pragma unroll
    for (int c = 0; c < 3; c++) {
        load_chunk(sb + c * STAGE_BYTES, tid, c, Ah, Al, Bh, Bl, brow, bcol, K);
        CP_COMMIT();
    }

    for (int c = 0; c < NCHUNK; c++) {
        const uint32_t so = sb + (c & (NSTAGE - 1)) * STAGE_BYTES;
        CP_WAIT2();
        __syncthreads();

#pragma unroll
        for (int ks = 0; ks < 2; ks++) {
            uint32_t afh[4][4], afl[4][4], bfh[2][4], bfl[2][4];
#pragma unroll
            for (int mt = 0; mt < 4; mt++) {
                int c16 = (ks << 1) + (lane >> 4);
                uint32_t a = so + arow[mt] * 64 + ((c16 ^ asel[mt]) << 4);
                ldsm4(afh[mt], a);
                ldsm4(afl[mt], a + SUB_BYTES);
            }
#pragma unroll
            for (int np = 0; np < 2; np++) {
                int c16 = (ks << 1) + bkh;
                uint32_t b = so + 2 * SUB_BYTES + brow_f[np] * 64 + ((c16 ^ bsel[np]) << 4);
                ldsm4(bfh[np], b);
                ldsm4(bfl[np], b + SUB_BYTES);
            }
#pragma unroll
            for (int mt = 0; mt < 4; mt++)
#pragma unroll
                for (int nt = 0; nt < 4; nt++) {
                    uint32_t* bh2 = &bfh[nt >> 1][(nt & 1) << 1];
                    uint32_t* bl2 = &bfl[nt >> 1][(nt & 1) << 1];
                    mma16816(acc[mt][nt], afh[mt], bh2);
                    mma16816(acc[mt][nt], afh[mt], bl2);
                    mma16816(acc[mt][nt], afl[mt], bh2);
                }
        }

        const int cn = c + 3;
        if (cn < NCHUNK)
            load_chunk(sb + (cn & (NSTAGE - 1)) * STAGE_BYTES, tid, cn,
                       Ah, Al, Bh, Bl, brow, bcol, K);
        CP_COMMIT();
    }

    // epilogue: fragment -> gmem with bias (float2 stores, 32B sectors)
#pragma unroll
    for (int mt = 0; mt < 4; mt++) {
        int r0 = brow + m0 + mt * 16 + (lane >> 2);
#pragma unroll
        for (int nt = 0; nt < 4; nt++) {
            int col = bcol + n0 + nt * 8 + ((lane & 3) << 1);
            float2 bv = *(const float2*)(bias + col);
            float2 v0 = make_float2(acc[mt][nt][0] + bv.x, acc[mt][nt][1] + bv.y);
            float2 v1 = make_float2(acc[mt][nt][2] + bv.x, acc[mt][nt][3] + bv.y);
            *(float2*)(C + (size_t)r0 * N + col)       = v0;
            *(float2*)(C + (size_t)(r0 + 8) * N + col) = v1;
        }
    }
}

// ---------------------------------------------------------------------------
// Flash-style causal attention, fp32 (unchanged passing version)
// ---------------------------------------------------------------------------
__global__ __launch_bounds__(256, 2)
void attn_kernel(const float* __restrict__ qkv, float* __restrict__ outp)
{
    __shared__ float4 Qs[64][16];
    __shared__ float4 KPs[64][16];
    __shared__ float4 Vs[64][16];

    const int t  = threadIdx.x;
    const int tx = t & 15;
    const int ty = t >> 4;
    const int qt = (int)(gridDim.x - 1u - blockIdx.x);
    const int h  = blockIdx.y;
    const int b  = blockIdx.z;
    const int qrow0 = b * Sn + qt * 64;

    const int lr = t >> 4;
    const int lk = t & 15;

#pragma unroll
    for (int p = 0; p < 4; p++) {
        int j = lr + (p << 4);
        Qs[j][lk ^ (j & 15)] =
            *(const float4*)(qkv + (size_t)(qrow0 + j) * TC + h * DKc + (lk << 2));
    }

    float o[4][4];
    float mprev[4], l[4];
#pragma unroll
    for (int i = 0; i < 4; i++) {
        mprev[i] = -1e30f;
        l[i] = 0.f;
#pragma unroll
        for (int m = 0; m < 4; m++) o[i][m] = 0.f;
    }

    for (int jt = 0; jt <= qt; jt++) {
        const int krow0 = b * Sn + jt * 64;
        __syncthreads();
#pragma unroll
        for (int p = 0; p < 4; p++) {
            int j = lr + (p << 4);
            size_t base = (size_t)(krow0 + j) * TC + h * DKc + (lk << 2);
            KPs[j][lk ^ (j & 15)] = *(const float4*)(qkv + base + Dm);
            Vs[j][lk ^ (j & 15)]  = *(const float4*)(qkv + base + 2 * Dm);
        }
        __syncthreads();

        float s[4][4];
#pragma unroll
        for (int i = 0; i < 4; i++)
#pragma unroll
            for (int m = 0; m < 4; m++) s[i][m] = 0.f;

#pragma unroll
        for (int k4 = 0; k4 < 16; k4++) {
            float4 q[4], kk[4];
#pragma unroll
            for (int i = 0; i < 4; i++) {
                int r = (ty << 2) + i;
                q[i] = Qs[r][k4 ^ (r & 15)];
            }
#pragma unroll
            for (int m = 0; m < 4; m++)
                kk[m] = KPs[tx + (m << 4)][k4 ^ tx];
#pragma unroll
            for (int i = 0; i < 4; i++)
#pragma unroll
                for (int m = 0; m < 4; m++) {
                    s[i][m] = fmaf(q[i].x, kk[m].x, s[i][m]);
                    s[i][m] = fmaf(q[i].y, kk[m].y, s[i][m]);
                    s[i][m] = fmaf(q[i].z, kk[m].z, s[i][m]);
                    s[i][m] = fmaf(q[i].w, kk[m].w, s[i][m]);
                }
        }

        const bool diag = (jt == qt);
#pragma unroll
        for (int i = 0; i < 4; i++) {
            int r = (ty << 2) + i;
#pragma unroll
            for (int m = 0; m < 4; m++) {
                float v = s[i][m] * 0.125f;
                if (diag && (tx + (m << 4)) > r) v = -1e30f;
                s[i][m] = v;
            }
            float tmax = fmaxf(fmaxf(s[i][0], s[i][1]), fmaxf(s[i][2], s[i][3]));
#pragma unroll
            for (int off = 1; off < 16; off <<= 1)
                tmax = fmaxf(tmax, __shfl_xor_sync(0xffffffffu, tmax, off));
            float mnew = fmaxf(mprev[i], tmax);
            float corr = __expf(mprev[i] - mnew);
            float ts = 0.f;
#pragma unroll
            for (int m = 0; m < 4; m++) {
                s[i][m] = __expf(s[i][m] - mnew);
                ts += s[i][m];
            }
#pragma unroll
            for (int off = 1; off < 16; off <<= 1)
                ts += __shfl_xor_sync(0xffffffffu, ts, off);
            l[i] = l[i] * corr + ts;
            mprev[i] = mnew;
#pragma unroll
            for (int m = 0; m < 4; m++) o[i][m] *= corr;
        }

        __syncthreads();
#pragma unroll
        for (int i = 0; i < 4; i++) {
            int r = (ty << 2) + i;
#pragma unroll
            for (int m = 0; m < 4; m++) {
                int c = tx + (m << 4);
                ((float*)&KPs[r][(c >> 2) ^ (r & 15)])[c & 3] = s[i][m];
            }
        }
        __syncthreads();

#pragma unroll
        for (int j4 = 0; j4 < 16; j4++) {
            float4 pp[4];
#pragma unroll
            for (int i = 0; i < 4; i++) {
                int r = (ty << 2) + i;
                pp[i] = KPs[r][j4 ^ (r & 15)];
            }
#pragma unroll
            for (int jj = 0; jj < 4; jj++) {
                int j = (j4 << 2) + jj;
                float pv[4] = { ((float*)&pp[0])[jj], ((float*)&pp[1])[jj],
                                ((float*)&pp[2])[jj], ((float*)&pp[3])[jj] };
                float vv[4];
#pragma unroll
                for (int m = 0; m < 4; m++) {
                    int c = tx + (m << 4);
                    vv[m] = ((const float*)&Vs[j][(c >> 2) ^ (j & 15)])[c & 3];
                }
#pragma unroll
                for (int i = 0; i < 4; i++)
#pragma unroll
                    for (int m = 0; m < 4; m++)
                        o[i][m] = fmaf(pv[i], vv[m], o[i][m]);
            }
        }
    }

#pragma unroll
    for (int i = 0; i < 4; i++) {
        int r = (ty << 2) + i;
        float inv = 1.f / l[i];
#pragma unroll
        for (int m = 0; m < 4; m++) {
            int c = tx + (m << 4);
            outp[(size_t)(qrow0 + r) * Dm + h * DKc + c] = o[i][m] * inv;
        }
    }
}

// ---------------------------------------------------------------------------
extern "C" void kernel_launch(void* const* d_in, const int* in_sizes, int n_in,
                              void* d_out, int out_size)
{
    const float* x     = (const float*)d_in[0];
    // d_in[1] = causal mask (int32) — causality hardcoded, unused
    const float* w_qkv = (const float*)d_in[2];
    const float* b_qkv = (const float*)d_in[3];
    const float* w_out = (const float*)d_in[4];
    const float* b_out = (const float*)d_in[5];
    float* out = (float*)d_out;

    float *qkv = nullptr, *attn = nullptr;
    __nv_bfloat16 *ah, *al, *bh, *bl;
    cudaGetSymbolAddress((void**)&qkv, g_qkv);
    cudaGetSymbolAddress((void**)&attn, g_attn);
    cudaGetSymbolAddress((void**)&ah, g_ah);
    cudaGetSymbolAddress((void**)&al, g_al);
    cudaGetSymbolAddress((void**)&bh, g_bh);
    cudaGetSymbolAddress((void**)&bl, g_bl);

    cudaFuncSetAttribute(gemm_bf16x3, cudaFuncAttributeMaxDynamicSharedMemorySize,
                         GEMM_DSMEM);

    // 1) splits for QKV gemm
    transpose_split_kernel<<<dim3(TC / 32, Dm / 32), dim3(32, 8)>>>(w_qkv, bh, bl, Dm, TC);
    split_kernel<<<(Mrows * Dm / 4 + 255) / 256, 256>>>(x, ah, al, Mrows * Dm / 4);

    // 2) QKV projection: [4096,1024] @ [1024,3072] + b  (HMMA bf16x3)
    gemm_bf16x3<<<dim3(TC / 128, Mrows / 128), 256, GEMM_DSMEM>>>(
        ah, al, bh, bl, b_qkv, qkv, TC, Dm);

    // 3) causal flash attention (fp32)
    attn_kernel<<<dim3(Sn / 64, Hn, Bn), 256>>>(qkv, attn);

    // 4) splits for out gemm
    transpose_split_kernel<<<dim3(Dm / 32, Dm / 32), dim3(32, 8)>>>(w_out, bh, bl, Dm, Dm);
    split_kernel<<<(Mrows * Dm / 4 + 255) / 256, 256>>>(attn, ah, al, Mrows * Dm / 4);

    // 5) output projection: [4096,1024] @ [1024,1024] + b
    gemm_bf16x3<<<dim3(Dm / 128, Mrows / 128), 256, GEMM_DSMEM>>>(
        ah, al, bh, bl, b_out, out, Dm, Dm);
}

// round 6
// speedup vs baseline: 2.9712x; 2.1075x over previous
#include <cuda_runtime.h>
#include <cuda_bf16.h>
#include <cstdint>

// Problem constants
#define Bn   2
#define Sn   2048
#define Dm   1024
#define Hn   16
#define DKc  64
#define Mrows 4096          // B*S
#define TC   3072           // 3*Dm

// Scratch (allocation-free: __device__ globals)
__device__ __nv_bfloat16 g_qh[(size_t)Mrows * TC];  // qkv hi
__device__ __nv_bfloat16 g_ql[(size_t)Mrows * TC];  // qkv lo
__device__ __nv_bfloat16 g_ah[(size_t)Mrows * Dm];  // A hi (x-split, then attn out)
__device__ __nv_bfloat16 g_al[(size_t)Mrows * Dm];  // A lo
__device__ __nv_bfloat16 g_bh[(size_t)TC * Dm];     // B^T hi
__device__ __nv_bfloat16 g_bl[(size_t)TC * Dm];     // B^T lo

// ---------------------------------------------------------------------------
// PTX helpers (baseline-PTX only: cp.async, ldmatrix, mma.sync)
// ---------------------------------------------------------------------------
__device__ __forceinline__ uint32_t smem_u32(const void* p) {
    return (uint32_t)__cvta_generic_to_shared(p);
}
#define CP_ASYNC16(dst, src) \
    asm volatile("cp.async.cg.shared.global [%0], [%1], 16;" :: "r"(dst), "l"(src))
#define CP_COMMIT() asm volatile("cp.async.commit_group;" ::: "memory")
#define CP_WAIT2()  asm volatile("cp.async.wait_group 2;" ::: "memory")
#define CP_WAIT1()  asm volatile("cp.async.wait_group 1;" ::: "memory")
#define CP_WAIT0()  asm volatile("cp.async.wait_group 0;" ::: "memory")

__device__ __forceinline__ void ldsm4(uint32_t* r, uint32_t addr) {
    asm volatile("ldmatrix.sync.aligned.m8n8.x4.shared.b16 {%0,%1,%2,%3}, [%4];"
        : "=r"(r[0]), "=r"(r[1]), "=r"(r[2]), "=r"(r[3]) : "r"(addr));
}
__device__ __forceinline__ void ldsm4t(uint32_t* r, uint32_t addr) {
    asm volatile("ldmatrix.sync.aligned.m8n8.x4.trans.shared.b16 {%0,%1,%2,%3}, [%4];"
        : "=r"(r[0]), "=r"(r[1]), "=r"(r[2]), "=r"(r[3]) : "r"(addr));
}
__device__ __forceinline__ void mma16816(float* d, const uint32_t* a, const uint32_t* b) {
    asm volatile(
        "mma.sync.aligned.m16n8k16.row.col.f32.bf16.bf16.f32 "
        "{%0,%1,%2,%3}, {%4,%5,%6,%7}, {%8,%9}, {%0,%1,%2,%3};"
        : "+f"(d[0]), "+f"(d[1]), "+f"(d[2]), "+f"(d[3])
        : "r"(a[0]), "r"(a[1]), "r"(a[2]), "r"(a[3]), "r"(b[0]), "r"(b[1]));
}
__device__ __forceinline__ float ex2(float x) {
    float r; asm("ex2.approx.f32 %0, %1;" : "=f"(r) : "f"(x)); return r;
}
// pack two f32 -> bf16x2 (lo in low half)
__device__ __forceinline__ uint32_t pk_bf2(float lo, float hi) {
    uint32_t r;
    asm("cvt.rn.bf16x2.f32 %0, %1, %2;" : "=r"(r) : "f"(hi), "f"(lo));
    return r;
}
__device__ __forceinline__ float bf16_rt(float v) {   // round-trip through bf16
    return __bfloat162float(__float2bfloat16(v));
}

// ---------------------------------------------------------------------------
// fp32 -> bf16 hi/lo split (straight copy)
// ---------------------------------------------------------------------------
__global__ void split_kernel(const float* __restrict__ in,
                             __nv_bfloat16* __restrict__ hi,
                             __nv_bfloat16* __restrict__ lo, int n4)
{
    int i = blockIdx.x * blockDim.x + threadIdx.x;
    if (i >= n4) return;
    float4 v = ((const float4*)in)[i];
    float vv[4] = {v.x, v.y, v.z, v.w};
    uint32_t h2[2], l2[2];
#pragma unroll
    for (int p = 0; p < 2; p++) {
        float h0 = bf16_rt(vv[2*p]), h1 = bf16_rt(vv[2*p+1]);
        h2[p] = pk_bf2(vv[2*p], vv[2*p+1]);        // rn-rounded hi
        // recompute hi actually used (rn) for residual:
        __nv_bfloat162 hh = *(__nv_bfloat162*)&h2[p];
        float f0 = __bfloat162float(hh.x), f1 = __bfloat162float(hh.y);
        l2[p] = pk_bf2(vv[2*p] - f0, vv[2*p+1] - f1);
        (void)h0; (void)h1;
    }
    ((uint32_t*)hi)[2*i]   = h2[0];
    ((uint32_t*)hi)[2*i+1] = h2[1];
    ((uint32_t*)lo)[2*i]   = l2[0];
    ((uint32_t*)lo)[2*i+1] = l2[1];
}

// ---------------------------------------------------------------------------
// fp32 [K][N] -> bf16 hi/lo [N][K] (transpose + split), 32x32 tiles
// ---------------------------------------------------------------------------
__global__ void transpose_split_kernel(const float* __restrict__ in,
                                       __nv_bfloat16* __restrict__ hi,
                                       __nv_bfloat16* __restrict__ lo,
                                       int K, int N)
{
    __shared__ float t[32][33];
    int bx = blockIdx.x << 5;
    int by = blockIdx.y << 5;
    int x = threadIdx.x;
    int y = threadIdx.y;
#pragma unroll
    for (int i = 0; i < 32; i += 8)
        t[y + i][x] = in[(size_t)(by + y + i) * N + bx + x];
    __syncthreads();
#pragma unroll
    for (int i = 0; i < 32; i += 8) {
        float v = t[x][y + i];
        float h = bf16_rt(v);
        size_t o = (size_t)(bx + y + i) * K + by + x;
        hi[o] = __float2bfloat16(v);
        lo[o] = __float2bfloat16(v - h);
    }
}

// ---------------------------------------------------------------------------
// HMMA bf16-split GEMM: C[M,N] = A[M,K] @ BT[N,K]^T + bias
// 128x128x32 CTA tile, 8 warps of 64x32, 4-stage cp.async pipeline.
// SPLIT_OUT=1: write hi/lo bf16 (Ch/Cl); else fp32 C.
// ---------------------------------------------------------------------------
#define SUB_BYTES  8192
#define STAGE_BYTES (4 * SUB_BYTES)
#define NSTAGE 4
#define GEMM_DSMEM (NSTAGE * STAGE_BYTES)  // 128 KB

__device__ __forceinline__ void load_chunk(
    uint32_t so, int tid, int chunk,
    const __nv_bfloat16* __restrict__ Ah, const __nv_bfloat16* __restrict__ Al,
    const __nv_bfloat16* __restrict__ Bh, const __nv_bfloat16* __restrict__ Bl,
    int brow, int bcol, int K)
{
    const int k0 = chunk << 5;
#pragma unroll
    for (int p = 0; p < 2; p++) {
        int r   = (tid >> 2) + (p << 6);
        int c16 = tid & 3;
        uint32_t dst = so + r * 64 + ((c16 ^ ((r >> 1) & 3)) << 4);
        size_t ga = (size_t)(brow + r) * K + k0 + (c16 << 3);
        size_t gb = (size_t)(bcol + r) * K + k0 + (c16 << 3);
        CP_ASYNC16(dst,                 Ah + ga);
        CP_ASYNC16(dst + SUB_BYTES,     Al + ga);
        CP_ASYNC16(dst + 2 * SUB_BYTES, Bh + gb);
        CP_ASYNC16(dst + 3 * SUB_BYTES, Bl + gb);
    }
}

template<int SPLIT_OUT>
__global__ __launch_bounds__(256, 1)
void gemm_bf16x3(const __nv_bfloat16* __restrict__ Ah, const __nv_bfloat16* __restrict__ Al,
                 const __nv_bfloat16* __restrict__ Bh, const __nv_bfloat16* __restrict__ Bl,
                 const float* __restrict__ bias, float* __restrict__ C,
                 __nv_bfloat16* __restrict__ Ch, __nv_bfloat16* __restrict__ Cl,
                 int N, int K)
{
    extern __shared__ char dsmem_raw[];
    const uint32_t sb = smem_u32(dsmem_raw);

    const int tid  = threadIdx.x;
    const int wid  = tid >> 5;
    const int lane = tid & 31;
    const int brow = blockIdx.y << 7;
    const int bcol = blockIdx.x << 7;
    const int NCHUNK = K >> 5;

    const int m0 = (wid & 1) << 6;
    const int n0 = (wid >> 1) << 5;

    float acc[4][4][4];
#pragma unroll
    for (int mt = 0; mt < 4; mt++)
#pragma unroll
        for (int nt = 0; nt < 4; nt++)
#pragma unroll
            for (int e = 0; e < 4; e++) acc[mt][nt][e] = 0.f;

    int arow[4], asel[4];
#pragma unroll
    for (int mt = 0; mt < 4; mt++) {
        arow[mt] = m0 + mt * 16 + (lane & 15);
        asel[mt] = (arow[mt] >> 1) & 3;
    }
    int brow_f[2], bsel[2], bkh = (lane >> 3) & 1;
#pragma unroll
    for (int np = 0; np < 2; np++) {
        brow_f[np] = n0 + np * 16 + ((lane >> 4) << 3) + (lane & 7);
        bsel[np] = (brow_f[np] >> 1) & 3;
    }

#pragma unroll
    for (int c = 0; c < 3; c++) {
        load_chunk(sb + c * STAGE_BYTES, tid, c, Ah, Al, Bh, Bl, brow, bcol, K);
        CP_COMMIT();
    }

    for (int c = 0; c < NCHUNK; c++) {
        const uint32_t so = sb + (c & (NSTAGE - 1)) * STAGE_BYTES;
        CP_WAIT2();
        __syncthreads();

#pragma unroll
        for (int ks = 0; ks < 2; ks++) {
            uint32_t afh[4][4], afl[4][4], bfh[2][4], bfl[2][4];
#pragma unroll
            for (int mt = 0; mt < 4; mt++) {
                int c16 = (ks << 1) + (lane >> 4);
                uint32_t a = so + arow[mt] * 64 + ((c16 ^ asel[mt]) << 4);
                ldsm4(afh[mt], a);
                ldsm4(afl[mt], a + SUB_BYTES);
            }
#pragma unroll
            for (int np = 0; np < 2; np++) {
                int c16 = (ks << 1) + bkh;
                uint32_t b = so + 2 * SUB_BYTES + brow_f[np] * 64 + ((c16 ^ bsel[np]) << 4);
                ldsm4(bfh[np], b);
                ldsm4(bfl[np], b + SUB_BYTES);
            }
#pragma unroll
            for (int mt = 0; mt < 4; mt++)
#pragma unroll
                for (int nt = 0; nt < 4; nt++) {
                    uint32_t* bh2 = &bfh[nt >> 1][(nt & 1) << 1];
                    uint32_t* bl2 = &bfl[nt >> 1][(nt & 1) << 1];
                    mma16816(acc[mt][nt], afh[mt], bh2);
                    mma16816(acc[mt][nt], afh[mt], bl2);
                    mma16816(acc[mt][nt], afl[mt], bh2);
                }
        }

        const int cn = c + 3;
        if (cn < NCHUNK)
            load_chunk(sb + (cn & (NSTAGE - 1)) * STAGE_BYTES, tid, cn,
                       Ah, Al, Bh, Bl, brow, bcol, K);
        CP_COMMIT();
    }

#pragma unroll
    for (int mt = 0; mt < 4; mt++) {
        int r0 = brow + m0 + mt * 16 + (lane >> 2);
#pragma unroll
        for (int nt = 0; nt < 4; nt++) {
            int col = bcol + n0 + nt * 8 + ((lane & 3) << 1);
            float2 bv = *(const float2*)(bias + col);
            float v0 = acc[mt][nt][0] + bv.x, v1 = acc[mt][nt][1] + bv.y;
            float v2 = acc[mt][nt][2] + bv.x, v3 = acc[mt][nt][3] + bv.y;
            if (SPLIT_OUT) {
                *(uint32_t*)(Ch + (size_t)r0 * N + col)       = pk_bf2(v0, v1);
                *(uint32_t*)(Ch + (size_t)(r0 + 8) * N + col) = pk_bf2(v2, v3);
                *(uint32_t*)(Cl + (size_t)r0 * N + col) =
                    pk_bf2(v0 - bf16_rt(v0), v1 - bf16_rt(v1));
                *(uint32_t*)(Cl + (size_t)(r0 + 8) * N + col) =
                    pk_bf2(v2 - bf16_rt(v2), v3 - bf16_rt(v3));
            } else {
                *(float2*)(C + (size_t)r0 * N + col)       = make_float2(v0, v1);
                *(float2*)(C + (size_t)(r0 + 8) * N + col) = make_float2(v2, v3);
            }
        }
    }
}

// ---------------------------------------------------------------------------
// HMMA flash attention (causal), bf16 hi/lo split inputs, fp32 softmax.
// CTA: 128 q-rows x (b,h); 8 warps x 16 rows. K-tiles of 64, double-buffered.
// smem: Qh 16K | Ql 16K | stage{0,1}: Kh 8K | Kl 8K | Vh 8K | Vl 8K  = 96 KB
// ---------------------------------------------------------------------------
#define ATT_SQL   16384
#define ATT_STG   32768
#define ATT_DSMEM (ATT_STG + 2 * 32768)   // 96 KB
#define SCL 0.1803368801111204f           // 0.125 * log2(e)

__device__ __forceinline__ void att_load_kv(
    uint32_t sb, int st, int tid, int krow0g, int qcol,
    const __nv_bfloat16* __restrict__ qh, const __nv_bfloat16* __restrict__ ql)
{
    const uint32_t so = sb + ATT_STG + st * 32768;
#pragma unroll
    for (int p = 0; p < 2; p++) {
        int i   = tid + (p << 8);
        int row = i >> 3;
        int c16 = i & 7;
        uint32_t dst = so + row * 128 + ((c16 ^ (row & 7)) << 4);
        size_t srcK = (size_t)(krow0g + row) * TC + Dm + qcol + (c16 << 3);
        size_t srcV = srcK + Dm;
        CP_ASYNC16(dst,         qh + srcK);
        CP_ASYNC16(dst + 8192,  ql + srcK);
        CP_ASYNC16(dst + 16384, qh + srcV);
        CP_ASYNC16(dst + 24576, ql + srcV);
    }
}

__global__ __launch_bounds__(256, 1)
void attn_hmma(const __nv_bfloat16* __restrict__ qh, const __nv_bfloat16* __restrict__ ql,
               __nv_bfloat16* __restrict__ oh, __nv_bfloat16* __restrict__ ol)
{
    extern __shared__ char smem_raw[];
    const uint32_t sb = smem_u32(smem_raw);
    const int tid  = threadIdx.x;
    const int wid  = tid >> 5;
    const int lane = tid & 31;
    const int qt   = (int)(gridDim.x - 1u - blockIdx.x);   // heavy tiles first
    const int h    = blockIdx.y;
    const int b    = blockIdx.z;
    const int qrow0 = b * Sn + qt * 128;   // global row base
    const int qcol  = h * DKc;

    // ---- load Q tile (hi/lo) + first KV stage, one commit group ----
#pragma unroll
    for (int p = 0; p < 4; p++) {
        int i   = tid + (p << 8);
        int row = i >> 3;
        int c16 = i & 7;
        uint32_t dst = sb + row * 128 + ((c16 ^ (row & 7)) << 4);
        size_t src = (size_t)(qrow0 + row) * TC + qcol + (c16 << 3);
        CP_ASYNC16(dst,           qh + src);
        CP_ASYNC16(dst + ATT_SQL, ql + src);
    }
    att_load_kv(sb, 0, tid, b * Sn, qcol, qh, ql);
    CP_COMMIT();

    const int m0 = wid << 4;           // warp's q-row base (0..112)
    const int ar = m0 + (lane & 15);   // A ldsm row
    const int asw = ar & 7;
    const int bkh = (lane >> 3) & 1;
    const int vg  = lane >> 3;

    float o[8][4];
#pragma unroll
    for (int nt = 0; nt < 8; nt++)
#pragma unroll
        for (int e = 0; e < 4; e++) o[nt][e] = 0.f;
    float mrow0 = -1e30f, mrow1 = -1e30f, lrow0 = 0.f, lrow1 = 0.f;

    const int njt = 2 * (qt + 1);
    const int gr0 = qt * 128 + m0 + (lane >> 2);   // within-sequence q index
    const int gr1 = gr0 + 8;

    for (int jt = 0; jt < njt; jt++) {
        const int cur = jt & 1;
        if (jt + 1 < njt) {
            att_load_kv(sb, cur ^ 1, tid, b * Sn + (jt + 1) * 64, qcol, qh, ql);
            CP_COMMIT();
            CP_WAIT1();
        } else {
            CP_WAIT0();
        }
        __syncthreads();

        const uint32_t soK = sb + ATT_STG + cur * 32768;
        const uint32_t soV = soK + 16384;

        // ---- S = Q K^T (3-term split) ----
        float s[8][4];
#pragma unroll
        for (int nt = 0; nt < 8; nt++)
#pragma unroll
            for (int e = 0; e < 4; e++) s[nt][e] = 0.f;

#pragma unroll
        for (int ks = 0; ks < 4; ks++) {
            uint32_t ah_[4], al_[4];
            uint32_t aaddr = sb + ar * 128 + ((((ks << 1) + (lane >> 4)) ^ asw) << 4);
            ldsm4(ah_, aaddr);
            ldsm4(al_, aaddr + ATT_SQL);
#pragma unroll
            for (int np = 0; np < 4; np++) {
                int brw = (np << 4) + ((lane >> 4) << 3) + (lane & 7);
                uint32_t baddr = soK + brw * 128 + ((((ks << 1) + bkh) ^ (brw & 7)) << 4);
                uint32_t bh_[4], bl_[4];
                ldsm4(bh_, baddr);
                ldsm4(bl_, baddr + 8192);
#pragma unroll
                for (int q = 0; q < 2; q++) {
                    float* sf = s[np * 2 + q];
                    mma16816(sf, ah_, &bh_[q << 1]);
                    mma16816(sf, ah_, &bl_[q << 1]);
                    mma16816(sf, al_, &bh_[q << 1]);
                }
            }
        }

        // ---- scale (exp2 domain), causal mask ----
        const bool diag = (jt >= 2 * qt);
        const int kbase = jt * 64 + ((lane & 3) << 1);
#pragma unroll
        for (int nt = 0; nt < 8; nt++) {
#pragma unroll
            for (int e = 0; e < 4; e++) s[nt][e] *= SCL;
            if (diag) {
                int kc = kbase + nt * 8;
                if (kc     > gr0) s[nt][0] = -1e30f;
                if (kc + 1 > gr0) s[nt][1] = -1e30f;
                if (kc     > gr1) s[nt][2] = -1e30f;
                if (kc + 1 > gr1) s[nt][3] = -1e30f;
            }
        }

        // ---- online softmax (rows r0, r1) ----
        float mx0 = -1e30f, mx1 = -1e30f;
#pragma unroll
        for (int nt = 0; nt < 8; nt++) {
            mx0 = fmaxf(mx0, fmaxf(s[nt][0], s[nt][1]));
            mx1 = fmaxf(mx1, fmaxf(s[nt][2], s[nt][3]));
        }
        mx0 = fmaxf(mx0, __shfl_xor_sync(0xffffffffu, mx0, 1));
        mx0 = fmaxf(mx0, __shfl_xor_sync(0xffffffffu, mx0, 2));
        mx1 = fmaxf(mx1, __shfl_xor_sync(0xffffffffu, mx1, 1));
        mx1 = fmaxf(mx1, __shfl_xor_sync(0xffffffffu, mx1, 2));
        float mn0 = fmaxf(mrow0, mx0), mn1 = fmaxf(mrow1, mx1);
        float c0 = ex2(mrow0 - mn0), c1 = ex2(mrow1 - mn1);
        mrow0 = mn0; mrow1 = mn1;
        float sum0 = 0.f, sum1 = 0.f;
#pragma unroll
        for (int nt = 0; nt < 8; nt++) {
            s[nt][0] = ex2(s[nt][0] - mn0); sum0 += s[nt][0];
            s[nt][1] = ex2(s[nt][1] - mn0); sum0 += s[nt][1];
            s[nt][2] = ex2(s[nt][2] - mn1); sum1 += s[nt][2];
            s[nt][3] = ex2(s[nt][3] - mn1); sum1 += s[nt][3];
        }
        sum0 += __shfl_xor_sync(0xffffffffu, sum0, 1);
        sum0 += __shfl_xor_sync(0xffffffffu, sum0, 2);
        sum1 += __shfl_xor_sync(0xffffffffu, sum1, 1);
        sum1 += __shfl_xor_sync(0xffffffffu, sum1, 2);
        lrow0 = lrow0 * c0 + sum0;
        lrow1 = lrow1 * c1 + sum1;
#pragma unroll
        for (int nt = 0; nt < 8; nt++) {
            o[nt][0] *= c0; o[nt][1] *= c0;
            o[nt][2] *= c1; o[nt][3] *= c1;
        }

        // ---- O += P V (P split hi/lo; V^T via ldmatrix.trans) ----
#pragma unroll
        for (int ks = 0; ks < 4; ks++) {
            // P A-fragments from S fragments (C->A identity)
            float* pa = s[ks * 2];
            float* pb = s[ks * 2 + 1];
            uint32_t pah[4], pal[4];
            pah[0] = pk_bf2(pa[0], pa[1]);
            pah[1] = pk_bf2(pa[2], pa[3]);
            pah[2] = pk_bf2(pb[0], pb[1]);
            pah[3] = pk_bf2(pb[2], pb[3]);
            pal[0] = pk_bf2(pa[0] - bf16_rt(pa[0]), pa[1] - bf16_rt(pa[1]));
            pal[1] = pk_bf2(pa[2] - bf16_rt(pa[2]), pa[3] - bf16_rt(pa[3]));
            pal[2] = pk_bf2(pb[0] - bf16_rt(pb[0]), pb[1] - bf16_rt(pb[1]));
            pal[3] = pk_bf2(pb[2] - bf16_rt(pb[2]), pb[3] - bf16_rt(pb[3]));

            int vrow = (ks << 4) + ((vg & 1) << 3) + (lane & 7);
            int vsw  = vrow & 7;
#pragma unroll
            for (int np = 0; np < 4; np++) {
                int gran = (np << 1) + (vg >> 1);
                uint32_t vaddr = soV + vrow * 128 + ((gran ^ vsw) << 4);
                uint32_t vh_[4], vl_[4];
                ldsm4t(vh_, vaddr);
                ldsm4t(vl_, vaddr + 8192);
#pragma unroll
                for (int q = 0; q < 2; q++) {
                    float* of = o[np * 2 + q];
                    mma16816(of, pah, &vh_[q << 1]);
                    mma16816(of, pal, &vh_[q << 1]);
                    mma16816(of, pah, &vl_[q << 1]);
                }
            }
        }
        __syncthreads();   // compute done before next stage overwrite
    }

    // ---- normalize, split hi/lo, write to out-proj A buffers ----
    float inv0 = 1.f / lrow0, inv1 = 1.f / lrow1;
    const int row0 = qrow0 + m0 + (lane >> 2);
#pragma unroll
    for (int nt = 0; nt < 8; nt++) {
        int col = qcol + nt * 8 + ((lane & 3) << 1);
        float v0 = o[nt][0] * inv0, v1 = o[nt][1] * inv0;
        float v2 = o[nt][2] * inv1, v3 = o[nt][3] * inv1;
        *(uint32_t*)(oh + (size_t)row0 * Dm + col)       = pk_bf2(v0, v1);
        *(uint32_t*)(oh + (size_t)(row0 + 8) * Dm + col) = pk_bf2(v2, v3);
        *(uint32_t*)(ol + (size_t)row0 * Dm + col) =
            pk_bf2(v0 - bf16_rt(v0), v1 - bf16_rt(v1));
        *(uint32_t*)(ol + (size_t)(row0 + 8) * Dm + col) =
            pk_bf2(v2 - bf16_rt(v2), v3 - bf16_rt(v3));
    }
}

// ---------------------------------------------------------------------------
extern "C" void kernel_launch(void* const* d_in, const int* in_sizes, int n_in,
                              void* d_out, int out_size)
{
    const float* x     = (const float*)d_in[0];
    // d_in[1] = causal mask (int32) — causality hardcoded, unused
    const float* w_qkv = (const float*)d_in[2];
    const float* b_qkv = (const float*)d_in[3];
    const float* w_out = (const float*)d_in[4];
    const float* b_out = (const float*)d_in[5];
    float* out = (float*)d_out;

    __nv_bfloat16 *qh, *ql, *ah, *al, *bh, *bl;
    cudaGetSymbolAddress((void**)&qh, g_qh);
    cudaGetSymbolAddress((void**)&ql, g_ql);
    cudaGetSymbolAddress((void**)&ah, g_ah);
    cudaGetSymbolAddress((void**)&al, g_al);
    cudaGetSymbolAddress((void**)&bh, g_bh);
    cudaGetSymbolAddress((void**)&bl, g_bl);

    cudaFuncSetAttribute(gemm_bf16x3<1>, cudaFuncAttributeMaxDynamicSharedMemorySize,
                         GEMM_DSMEM);
    cudaFuncSetAttribute(gemm_bf16x3<0>, cudaFuncAttributeMaxDynamicSharedMemorySize,
                         GEMM_DSMEM);
    cudaFuncSetAttribute(attn_hmma, cudaFuncAttributeMaxDynamicSharedMemorySize,
                         ATT_DSMEM);

    // 1) operand prep for QKV gemm
    transpose_split_kernel<<<dim3(TC / 32, Dm / 32), dim3(32, 8)>>>(w_qkv, bh, bl, Dm, TC);
    split_kernel<<<(Mrows * Dm / 4 + 255) / 256, 256>>>(x, ah, al, Mrows * Dm / 4);

    // 2) QKV projection -> split bf16 qkv (no fp32 intermediate)
    gemm_bf16x3<1><<<dim3(TC / 128, Mrows / 128), 256, GEMM_DSMEM>>>(
        ah, al, bh, bl, b_qkv, nullptr, qh, ql, TC, Dm);

    // 3) causal flash attention (HMMA) -> split bf16 attn output in ah/al
    attn_hmma<<<dim3(Sn / 128, Hn, Bn), 256, ATT_DSMEM>>>(qh, ql, ah, al);

    // 4) operand prep for out gemm (weights only; A comes from attention)
    transpose_split_kernel<<<dim3(Dm / 32, Dm / 32), dim3(32, 8)>>>(w_out, bh, bl, Dm, Dm);

    // 5) output projection -> fp32 out
    gemm_bf16x3<0><<<dim3(Dm / 128, Mrows / 128), 256, GEMM_DSMEM>>>(
        ah, al, bh, bl, b_out, out, nullptr, nullptr, Dm, Dm);
}